// round 15
// baseline (speedup 1.0000x reference)
#include <cuda_runtime.h>
#include <cstdint>
#include <math_constants.h>

#define NT     65536
#define DIM    256
#define NE     1024
#define MCTA   32
#define BLOCK  512
#define CCAP   16

// ---------------- smem layout (bytes) ----------------
#define SA8   0              // z tile int8: 32 rows x 72 words (pair-permuted)    9216
#define SBB   9216           // 2 B chunk buffers x 10240 (k64 chunks)            20480
#define SQD   29696          // qd: 32 rows x 516 u32 words (s16 pairs)           66048
#define SE2   95744          // e2 all 1024 f32                                    4096
#define SZ2   99840          // row norms f32 [32]                                  128
#define SINV  99968          // per-row inv dot scale f32 [32]                      128
#define SWQ   100096         // per-row capture window (q units) [32] int           128
#define SSZ   100224         // per-row z quant scale f32 [32]                      128
#define SCN   100352         // cand count [32] int                                 128
#define SMINQ 100480         // min q per row [32] int                              128
#define SBI   100608         // best index [32] int                                 128
#define SCL   100736         // cand list [32][CCAP] int                           2048
#define SRED  102784         // loss reduction [512] double                        4096
#define SMEM_TOTAL 106880    // ~104.4 KB -> 2 CTAs/SM

#define A8_STRIDE_W  72
#define B_STRIDE_W   20      // 16 data + 4 pad words per code row in chunk
#define BBUF_BYTES   10240
#define QD_STRIDE_W  516

__device__ double g_loss_acc;
__device__ float  g_e2[NE];
__device__ unsigned g_cbmax_bits;
__device__ unsigned g_scmax_bits;
// pair-permuted int8 codebook: per code 256 bytes = 8 groups of 32 k;
// within each group's 8 words, stored[2q]=orig[q], stored[2q+1]=orig[q+4]
__device__ __align__(16) signed char g_cb8[NE * DIM];

#define CP16(dst, src) asm volatile("cp.async.cg.shared.global [%0], [%1], 16;" :: "r"(dst), "l"(src) : "memory")
#define CP_COMMIT()    asm volatile("cp.async.commit_group;" ::: "memory")
#define CP_WAIT1()     asm volatile("cp.async.wait_group 1;" ::: "memory")

__device__ __forceinline__ uint32_t smem_u32(const void* p) {
    uint32_t a;
    asm("{ .reg .u64 t; cvta.to.shared.u64 t, %1; cvt.u32.u64 %0, t; }" : "=r"(a) : "l"(p));
    return a;
}

__device__ __forceinline__ void mma_s8(int& c0, int& c1, int& c2, int& c3,
                                       uint32_t a0, uint32_t a1, uint32_t a2, uint32_t a3,
                                       uint32_t b0, uint32_t b1) {
    asm volatile("mma.sync.aligned.m16n8k32.row.col.s32.s8.s8.s32 "
                 "{%0,%1,%2,%3},{%4,%5,%6,%7},{%8,%9},{%0,%1,%2,%3};"
                 : "+r"(c0), "+r"(c1), "+r"(c2), "+r"(c3)
                 : "r"(a0), "r"(a1), "r"(a2), "r"(a3), "r"(b0), "r"(b1));
}

__device__ __forceinline__ int quant8(float v, float s) {
    int x = __float2int_rn(v * s);
    return max(-127, min(127, x));
}

// ---------------- prep1: e2 (fp64) + cb stats + zero loss ----------------
__global__ void vq_prep1_kernel(const float* __restrict__ cb) {
    int tid = threadIdx.x, lane = tid & 31;
    if (blockIdx.x == 0 && tid == 0) g_loss_acc = 0.0;
    int gw = blockIdx.x * 8 + (tid >> 5);
    #pragma unroll
    for (int i = 0; i < 4; i++) {
        int c = gw * 4 + i;
        const float* row = cb + (size_t)c * DIM;
        double s = 0.0; float sa = 0.0f, mx = 0.0f;
        #pragma unroll
        for (int j = 0; j < 8; j++) {
            float v = row[lane + 32 * j];
            s += (double)v * (double)v;
            sa += fabsf(v);
            mx = fmaxf(mx, fabsf(v));
        }
        #pragma unroll
        for (int o = 16; o; o >>= 1) {
            s  += __shfl_xor_sync(0xffffffffu, s, o);
            sa += __shfl_xor_sync(0xffffffffu, sa, o);
            mx = fmaxf(mx, __shfl_xor_sync(0xffffffffu, mx, o));
        }
        if (lane == 0) {
            g_e2[c] = (float)s;
            atomicMax(&g_cbmax_bits, __float_as_uint(mx));
            atomicMax(&g_scmax_bits, __float_as_uint(sa));
        }
    }
}

// ---------------- prep2: quantize codebook int8 pair-permuted ----------------
__global__ void vq_prep2_kernel(const float* __restrict__ cb) {
    float cbmax = __uint_as_float(g_cbmax_bits);
    float sc = (cbmax > 0.0f) ? 126.0f / cbmax : 1.0f;
    uint32_t* out8 = (uint32_t*)g_cb8;
    int base = blockIdx.x * 256 + threadIdx.x;
    #pragma unroll
    for (int i = 0; i < 8; i++) {
        int w = base + i * 8192;
        int n = w >> 6, m = w & 63;
        int G = m >> 3, p = m & 7;
        int o = (p & 1) ? ((p >> 1) + 4) : (p >> 1);
        int k0 = G * 32 + o * 4;
        const float* src = cb + (size_t)n * DIM + k0;
        int b0 = quant8(src[0], sc), b1 = quant8(src[1], sc);
        int b2 = quant8(src[2], sc), b3 = quant8(src[3], sc);
        out8[w] = (uint32_t)(b0 & 0xff) | ((uint32_t)(b1 & 0xff) << 8)
                | ((uint32_t)(b2 & 0xff) << 16) | ((uint32_t)(b3 & 0xff) << 24);
    }
}

// ---------------- main: 512 threads, 16 warps (2 M x 8 N), 2 CTAs/SM ----------------
__global__ __launch_bounds__(BLOCK, 2) void vq_main_kernel(
    const float* __restrict__ z,
    const float* __restrict__ cb,
    float* __restrict__ out)
{
    extern __shared__ char smem[];
    const uint32_t sbu = smem_u32(smem);
    uint32_t* a8w   = (uint32_t*)(smem + SA8);
    uint32_t* qd    = (uint32_t*)(smem + SQD);
    float*    e2s   = (float*)(smem + SE2);
    float*    z2s   = (float*)(smem + SZ2);
    float*    invs  = (float*)(smem + SINV);
    int*      wqs   = (int*)(smem + SWQ);
    float*    szs   = (float*)(smem + SSZ);
    int*      ccnt  = (int*)(smem + SCN);
    int*      minqs = (int*)(smem + SMINQ);
    int*      bi_s  = (int*)(smem + SBI);
    int*      clist = (int*)(smem + SCL);

    const int tid  = threadIdx.x;
    const int wid  = tid >> 5;
    const int lane = tid & 31;
    const int q    = lane & 3;
    const int lq   = lane >> 2;
    const int m0   = blockIdx.x * MCTA;
    const int mw   = (wid & 1) * 16;     // warp M base (2 warps in M)
    const int nw   = (wid >> 1) * 16;    // warp N base within 128-ntile (8 warps in N)

    const float cbmax = __uint_as_float(g_cbmax_bits);
    const float scmax = __uint_as_float(g_scmax_bits);
    const float sc  = (cbmax > 0.0f) ? 126.0f / cbmax : 1.0f;
    const float dcq = 0.5f / sc;

    // ---- e2 table, init ----
    #pragma unroll
    for (int i = 0; i < 2; i++) e2s[i * BLOCK + tid] = g_e2[i * BLOCK + tid];
    if (tid < MCTA) ccnt[tid] = 0;

    // ---- per-row stats (fp64 z2, sum|z|, max|z|): warp w owns rows 2w..2w+1 ----
    #pragma unroll
    for (int rr = 0; rr < 2; rr++) {
        int r = wid * 2 + rr;
        const float* zr = z + (size_t)(m0 + r) * DIM;
        double s = 0.0; float sa = 0.0f, mx = 0.0f;
        #pragma unroll
        for (int i = 0; i < 8; i++) {
            float v = zr[lane + 32 * i];
            s += (double)v * (double)v;
            sa += fabsf(v);
            mx = fmaxf(mx, fabsf(v));
        }
        #pragma unroll
        for (int o = 16; o; o >>= 1) {
            s  += __shfl_xor_sync(0xffffffffu, s, o);
            sa += __shfl_xor_sync(0xffffffffu, sa, o);
            mx = fmaxf(mx, __shfl_xor_sync(0xffffffffu, mx, o));
        }
        if (lane == 0) {
            float sz = (mx > 0.0f) ? 126.0f / mx : 1.0f;
            float dzr = 0.5f / sz;
            float E = dzr * scmax + dcq * sa + 256.0f * dzr * dcq;  // hard dot-err bound
            z2s[r]  = (float)s;
            szs[r]  = sz;
            invs[r] = 1.0f / (sz * sc);
            wqs[r]  = (int)(4.0f * E * 32768.0f) + 8;
        }
    }
    __syncthreads();

    // ---- stage A int8 pair-permuted (2048 words) ----
    #pragma unroll
    for (int i = 0; i < 4; i++) {
        int s = i * BLOCK + tid;
        int row = s >> 6, ow = s & 63;
        int G = ow >> 3, o = ow & 7;
        int k0 = G * 32 + o * 4;
        float sz = szs[row];
        const float* src = z + (size_t)(m0 + row) * DIM + k0;
        int b0 = quant8(src[0], sz), b1 = quant8(src[1], sz);
        int b2 = quant8(src[2], sz), b3 = quant8(src[3], sz);
        int dw = (o < 4) ? 2 * o : 2 * (o - 4) + 1;
        a8w[row * A8_STRIDE_W + G * 8 + dw] =
            (uint32_t)(b0 & 0xff) | ((uint32_t)(b1 & 0xff) << 8)
          | ((uint32_t)(b2 & 0xff) << 16) | ((uint32_t)(b3 & 0xff) << 24);
    }
    __syncthreads();

    // ---- B chunk loader: chunk c -> ntile c>>2, k64-chunk c&3, buffer c&1 ----
    auto load_chunk = [&](int c) {
        int nt = c >> 2, kc = c & 3;
        const char* src0 = (const char*)g_cb8 + (size_t)nt * 128 * 256 + kc * 64;
        uint32_t bbase = sbu + SBB + (c & 1) * BBUF_BYTES;
        int n = tid >> 2, seg = tid & 3;
        CP16(bbase + n * 80 + seg * 16, src0 + (size_t)n * 256 + seg * 16);
    };
    load_chunk(0); CP_COMMIT();
    load_chunk(1); CP_COMMIT();

    int acc[2][4];
    #pragma unroll
    for (int j = 0; j < 2; j++)
        #pragma unroll
        for (int e = 0; e < 4; e++) acc[j][e] = 0;

    const int r0 = mw + lq;
    const float inv0 = invs[r0], inv1 = invs[r0 + 8];

    for (int c = 0; c < 32; c++) {
        const int nt = c >> 2, kc = c & 3;
        CP_WAIT1();
        __syncthreads();      // chunk c resident for all

        const uint32_t* Bw = (const uint32_t*)(smem + SBB + (c & 1) * BBUF_BYTES);
        #pragma unroll
        for (int g = 0; g < 2; g++) {
            const int aw = (kc * 2 + g) * 8 + 2 * q;
            uint2 A0 = *(const uint2*)(a8w + r0 * A8_STRIDE_W + aw);
            uint2 A1 = *(const uint2*)(a8w + (r0 + 8) * A8_STRIDE_W + aw);
            #pragma unroll
            for (int j = 0; j < 2; j++) {
                int nl = nw + 8 * j + lq;
                uint2 B0 = *(const uint2*)(Bw + nl * B_STRIDE_W + g * 8 + 2 * q);
                mma_s8(acc[j][0], acc[j][1], acc[j][2], acc[j][3],
                       A0.x, A1.x, A0.y, A1.y, B0.x, B0.y);
            }
        }

        if (kc == 3) {
            // q16 = round((e2 - 2*isum*inv) * 2^15)
            #pragma unroll
            for (int j = 0; j < 2; j++) {
                int col0 = nt * 128 + nw + 8 * j + 2 * q;
                float e20 = e2s[col0], e21 = e2s[col0 + 1];
                int wIdx = (col0 >> 1);
                #pragma unroll
                for (int h = 0; h < 2; h++) {
                    float inv = h ? inv1 : inv0;
                    float s0 = e20 - 2.0f * ((float)acc[j][h * 2 + 0] * inv);
                    float s1 = e21 - 2.0f * ((float)acc[j][h * 2 + 1] * inv);
                    int q0 = max(-32767, min(32767, __float2int_rn(s0 * 32768.0f)));
                    int q1 = max(-32767, min(32767, __float2int_rn(s1 * 32768.0f)));
                    qd[(r0 + 8 * h) * QD_STRIDE_W + wIdx] =
                        ((uint32_t)(q1 & 0xffff) << 16) | (uint32_t)(q0 & 0xffff);
                    acc[j][h * 2 + 0] = 0;
                    acc[j][h * 2 + 1] = 0;
                }
            }
        }

        __syncthreads();      // all done with buffer (c&1) before overwrite
        if (c + 2 < 32) load_chunk(c + 2);
        CP_COMMIT();
    }
    __syncthreads();

    // ---- per-row FINAL min + capture (warp w owns rows 2w..2w+1, uint4 loads) ----
    for (int rr = 0; rr < 2; rr++) {
        int r = wid * 2 + rr;
        const uint4* row4 = (const uint4*)(qd + r * QD_STRIDE_W);
        uint4 v[4];
        int mn = 0x7fffffff;
        #pragma unroll
        for (int i = 0; i < 4; i++) {
            v[i] = row4[lane + 32 * i];
            const uint32_t* vw = (const uint32_t*)&v[i];
            #pragma unroll
            for (int w = 0; w < 4; w++) {
                int a = (int)(short)(vw[w] & 0xffff);
                int b = (int)(short)(vw[w] >> 16);
                mn = min(mn, min(a, b));
            }
        }
        #pragma unroll
        for (int o = 16; o; o >>= 1) mn = min(mn, __shfl_xor_sync(0xffffffffu, mn, o));
        int thr = mn + wqs[r];
        #pragma unroll
        for (int i = 0; i < 4; i++) {
            const uint32_t* vw = (const uint32_t*)&v[i];
            #pragma unroll
            for (int w = 0; w < 4; w++) {
                int a = (int)(short)(vw[w] & 0xffff);
                int b = (int)(short)(vw[w] >> 16);
                int colw = (lane + 32 * i) * 4 + w;
                if (a <= thr) {
                    int p = atomicAdd(&ccnt[r], 1);
                    if (p < CCAP) clist[r * CCAP + p] = 2 * colw;
                }
                if (b <= thr) {
                    int p = atomicAdd(&ccnt[r], 1);
                    if (p < CCAP) clist[r * CCAP + p] = 2 * colw + 1;
                }
            }
        }
        if (lane == 0) minqs[r] = mn;
    }
    __syncthreads();

    // ---- warp-parallel exact fp32 rescue (warp w owns rows 2w..2w+1) ----
    for (int rr = 0; rr < 2; rr++) {
        int r = wid * 2 + rr;
        const float z2f = z2s[r];
        const float* zr = z + (size_t)(m0 + r) * DIM;
        float zv[8];
        #pragma unroll
        for (int i = 0; i < 8; i++) zv[i] = zr[lane + 32 * i];

        float best = CUDART_INF_F; int bi = 0x7fffffff;
        int cnt = ccnt[r];
        int n_check = (cnt <= CCAP) ? cnt : NE;
        for (int p = 0; p < n_check; p++) {
            int cidx = (cnt <= CCAP) ? clist[r * CCAP + p] : p;
            const float* cr = cb + (size_t)cidx * DIM;
            float part = 0.0f;
            #pragma unroll
            for (int i = 0; i < 8; i++)
                part = fmaf(zv[i], __ldg(cr + lane + 32 * i), part);
            #pragma unroll
            for (int o = 16; o; o >>= 1)
                part += __shfl_xor_sync(0xffffffffu, part, o);
            float dd = (z2f - 2.0f * part) + e2s[cidx];
            if (dd < best || (dd == best && cidx < bi)) { best = dd; bi = cidx; }
        }
        if (lane == 0) bi_s[r] = bi;
    }
    __syncthreads();

    // ---- epilogue: z_q_st (exact ST rounding), indices, loss ----
    const int half = tid >> 8;          // 0/1: rows [0,16) / [16,32)
    const int col  = tid & 255;
    float lacc = 0.0f;
    #pragma unroll 4
    for (int it = 0; it < 16; it++) {
        int row = half * 16 + it;
        float zv = z[(size_t)(m0 + row) * DIM + col];
        float e  = __ldg(cb + (size_t)bi_s[row] * DIM + col);
        float dq = e - zv;                  // fl(z_q - z)
        float o  = zv + dq;                 // fl(z + fl(z_q - z))
        out[(size_t)(m0 + row) * DIM + col] = o;
        lacc = fmaf(dq, dq, lacc);
    }
    if (tid < MCTA)
        out[(size_t)NT * DIM + 1 + m0 + tid] = (float)bi_s[tid];

    double* red = (double*)(smem + SRED);
    red[tid] = (double)lacc;
    __syncthreads();
    #pragma unroll
    for (int s = 256; s > 0; s >>= 1) {
        if (tid < s) red[tid] += red[tid + s];
        __syncthreads();
    }
    if (tid == 0) atomicAdd(&g_loss_acc, red[0]);
}

__global__ void vq_loss_kernel(float* __restrict__ out) {
    out[(size_t)NT * DIM] = (float)(1.25 * g_loss_acc / ((double)NT * (double)DIM));
}

// ---------------------------------------------------------------------------
extern "C" void kernel_launch(void* const* d_in, const int* in_sizes, int n_in,
                              void* d_out, int out_size) {
    const float *z, *cb;
    if (in_sizes[0] == NT * DIM) { z = (const float*)d_in[0]; cb = (const float*)d_in[1]; }
    else                         { z = (const float*)d_in[1]; cb = (const float*)d_in[0]; }
    float* out = (float*)d_out;

    cudaFuncSetAttribute(vq_main_kernel,
                         cudaFuncAttributeMaxDynamicSharedMemorySize, SMEM_TOTAL);

    vq_prep1_kernel<<<32, 256>>>(cb);
    vq_prep2_kernel<<<32, 256>>>(cb);
    vq_main_kernel<<<NT / MCTA, BLOCK, SMEM_TOTAL>>>(z, cb, out);
    vq_loss_kernel<<<1, 1>>>(out);
}

// round 16
// speedup vs baseline: 5.4027x; 5.4027x over previous
#include <cuda_runtime.h>
#include <cstdint>
#include <math_constants.h>

#define NT     65536
#define DIM    256
#define NE     1024
#define MCTA   64
#define BLOCK  1024
#define CCAP   48

// ---------------- smem layout (bytes) ----------------
#define SA8   0              // z tile int8: 64 rows x 72 words (pair-permuted)   18432
#define SBB   18432          // 4 B chunk buffers x 10240 (k64 chunks)            40960
#define SQD   59392          // qd: 64 rows x 516 u32 (s16 pairs); pre-mainloop: z fp32 tile 64x260 f32 (66560)  132096
#define SE2   191488         // e2 all 1024 f32                                    4096
#define SZ2   195584         // row norms f32 [64]                                  256
#define SINV  195840         // per-row inv dot scale f32 [64]                      256
#define SWQ   196096         // per-row capture window (q units) [64] int           256
#define SSZ   196352         // per-row z quant scale f32 [64]                      256
#define SCN   196608         // cand count [64] int                                 256
#define SBI   196864         // best index [64] int                                 256
#define SCL   197120         // cand list [64][CCAP] int                          12288
#define SMEM_TOTAL 209408

#define A8_STRIDE_W  72
#define B_STRIDE_W   20      // 16 data + 4 pad words per code row in chunk
#define BBUF_BYTES   10240
#define QD_STRIDE_W  516
#define ZF_STRIDE    260     // fp32 z staging stride (floats)

__device__ double g_loss_acc;
__device__ float  g_e2[NE];
__device__ unsigned g_cbmax_bits;
__device__ unsigned g_scmax_bits;
// pair-permuted int8 codebook: per code 256 bytes = 8 groups of 32 k;
// within each group's 8 words, stored[2q]=orig[q], stored[2q+1]=orig[q+4]
__device__ __align__(16) signed char g_cb8[NE * DIM];

#define CP16(dst, src) asm volatile("cp.async.cg.shared.global [%0], [%1], 16;" :: "r"(dst), "l"(src) : "memory")
#define CP_COMMIT()    asm volatile("cp.async.commit_group;" ::: "memory")
#define CP_WAIT2()     asm volatile("cp.async.wait_group 2;" ::: "memory")

__device__ __forceinline__ uint32_t smem_u32(const void* p) {
    uint32_t a;
    asm("{ .reg .u64 t; cvta.to.shared.u64 t, %1; cvt.u32.u64 %0, t; }" : "=r"(a) : "l"(p));
    return a;
}

__device__ __forceinline__ void mma_s8(int& c0, int& c1, int& c2, int& c3,
                                       uint32_t a0, uint32_t a1, uint32_t a2, uint32_t a3,
                                       uint32_t b0, uint32_t b1) {
    asm volatile("mma.sync.aligned.m16n8k32.row.col.s32.s8.s8.s32 "
                 "{%0,%1,%2,%3},{%4,%5,%6,%7},{%8,%9},{%0,%1,%2,%3};"
                 : "+r"(c0), "+r"(c1), "+r"(c2), "+r"(c3)
                 : "r"(a0), "r"(a1), "r"(a2), "r"(a3), "r"(b0), "r"(b1));
}

__device__ __forceinline__ int quant8(float v, float s) {
    int x = __float2int_rn(v * s);
    return max(-127, min(127, x));
}

// ---------------- prep1: e2 (fp64) + cb stats + zero loss ----------------
__global__ void vq_prep1_kernel(const float* __restrict__ cb) {
    int tid = threadIdx.x, lane = tid & 31;
    if (blockIdx.x == 0 && tid == 0) g_loss_acc = 0.0;
    int gw = blockIdx.x * 8 + (tid >> 5);
    #pragma unroll
    for (int i = 0; i < 4; i++) {
        int c = gw * 4 + i;
        const float* row = cb + (size_t)c * DIM;
        double s = 0.0; float sa = 0.0f, mx = 0.0f;
        #pragma unroll
        for (int j = 0; j < 8; j++) {
            float v = row[lane + 32 * j];
            s += (double)v * (double)v;
            sa += fabsf(v);
            mx = fmaxf(mx, fabsf(v));
        }
        #pragma unroll
        for (int o = 16; o; o >>= 1) {
            s  += __shfl_xor_sync(0xffffffffu, s, o);
            sa += __shfl_xor_sync(0xffffffffu, sa, o);
            mx = fmaxf(mx, __shfl_xor_sync(0xffffffffu, mx, o));
        }
        if (lane == 0) {
            g_e2[c] = (float)s;
            atomicMax(&g_cbmax_bits, __float_as_uint(mx));
            atomicMax(&g_scmax_bits, __float_as_uint(sa));
        }
    }
}

// ---------------- prep2: quantize codebook int8 pair-permuted ----------------
__global__ void vq_prep2_kernel(const float* __restrict__ cb) {
    float cbmax = __uint_as_float(g_cbmax_bits);
    float sc = (cbmax > 0.0f) ? 126.0f / cbmax : 1.0f;
    uint32_t* out8 = (uint32_t*)g_cb8;
    int base = blockIdx.x * 256 + threadIdx.x;
    #pragma unroll
    for (int i = 0; i < 8; i++) {
        int w = base + i * 8192;
        int n = w >> 6, m = w & 63;
        int G = m >> 3, p = m & 7;
        int o = (p & 1) ? ((p >> 1) + 4) : (p >> 1);
        int k0 = G * 32 + o * 4;
        const float* src = cb + (size_t)n * DIM + k0;
        int b0 = quant8(src[0], sc), b1 = quant8(src[1], sc);
        int b2 = quant8(src[2], sc), b3 = quant8(src[3], sc);
        out8[w] = (uint32_t)(b0 & 0xff) | ((uint32_t)(b1 & 0xff) << 8)
                | ((uint32_t)(b2 & 0xff) << 16) | ((uint32_t)(b3 & 0xff) << 24);
    }
}

// ---------------- main: 1024 threads, 32 warps (4 M x 8 N) ----------------
__global__ __launch_bounds__(BLOCK) void vq_main_kernel(
    const float* __restrict__ z,
    const float* __restrict__ cb,
    float* __restrict__ out)
{
    extern __shared__ char smem[];
    const uint32_t sbu = smem_u32(smem);
    uint32_t* a8w   = (uint32_t*)(smem + SA8);
    uint32_t* qd    = (uint32_t*)(smem + SQD);
    float*    zf    = (float*)(smem + SQD);     // pre-mainloop overlay
    float*    e2s   = (float*)(smem + SE2);
    float*    z2s   = (float*)(smem + SZ2);
    float*    invs  = (float*)(smem + SINV);
    int*      wqs   = (int*)(smem + SWQ);
    float*    szs   = (float*)(smem + SSZ);
    int*      ccnt  = (int*)(smem + SCN);
    int*      bi_s  = (int*)(smem + SBI);
    int*      clist = (int*)(smem + SCL);

    const int tid  = threadIdx.x;
    const int wid  = tid >> 5;
    const int lane = tid & 31;
    const int q    = lane & 3;
    const int lq   = lane >> 2;
    const int m0   = blockIdx.x * MCTA;
    const int mw   = (wid & 3) * 16;     // warp M base (4 warps in M)
    const int nw   = (wid >> 2) * 16;    // warp N base within 128-ntile (8 warps in N)

    const float cbmax = __uint_as_float(g_cbmax_bits);
    const float scmax = __uint_as_float(g_scmax_bits);
    const float sc  = (cbmax > 0.0f) ? 126.0f / cbmax : 1.0f;
    const float dcq = 0.5f / sc;

    // ---- stage z fp32 tile (single coalesced global pass), e2 table ----
    e2s[tid] = g_e2[tid];
    if (tid < MCTA) ccnt[tid] = 0;
    #pragma unroll
    for (int i = 0; i < 4; i++) {
        int s = i * BLOCK + tid;         // 4096 float4
        int row = s >> 6, c4 = s & 63;
        float4 v = *(const float4*)(z + (size_t)(m0 + row) * DIM + c4 * 4);
        *(float4*)(zf + row * ZF_STRIDE + c4 * 4) = v;
    }
    __syncthreads();

    // ---- per-row stats from smem (fp64 z2, sum|z|, max|z|): warp w owns rows 2w..2w+1 ----
    #pragma unroll
    for (int rr = 0; rr < 2; rr++) {
        int r = wid * 2 + rr;
        const float* zr = zf + r * ZF_STRIDE;
        double s = 0.0; float sa = 0.0f, mx = 0.0f;
        #pragma unroll
        for (int i = 0; i < 8; i++) {
            float v = zr[lane + 32 * i];
            s += (double)v * (double)v;
            sa += fabsf(v);
            mx = fmaxf(mx, fabsf(v));
        }
        #pragma unroll
        for (int o = 16; o; o >>= 1) {
            s  += __shfl_xor_sync(0xffffffffu, s, o);
            sa += __shfl_xor_sync(0xffffffffu, sa, o);
            mx = fmaxf(mx, __shfl_xor_sync(0xffffffffu, mx, o));
        }
        if (lane == 0) {
            float sz = (mx > 0.0f) ? 126.0f / mx : 1.0f;
            float dzr = 0.5f / sz;
            float E = dzr * scmax + dcq * sa + 256.0f * dzr * dcq;  // hard dot-err bound
            z2s[r]  = (float)s;
            szs[r]  = sz;
            invs[r] = 1.0f / (sz * sc);
            wqs[r]  = (int)(4.0f * E * 32768.0f) + 8;
        }
    }
    __syncthreads();

    // ---- stage A int8 pair-permuted from smem fp32 (4096 words) ----
    #pragma unroll
    for (int i = 0; i < 4; i++) {
        int s = i * BLOCK + tid;
        int row = s >> 6, ow = s & 63;
        int G = ow >> 3, o = ow & 7;
        int k0 = G * 32 + o * 4;
        float sz = szs[row];
        const float* src = zf + row * ZF_STRIDE + k0;
        int b0 = quant8(src[0], sz), b1 = quant8(src[1], sz);
        int b2 = quant8(src[2], sz), b3 = quant8(src[3], sz);
        int dw = (o < 4) ? 2 * o : 2 * (o - 4) + 1;
        a8w[row * A8_STRIDE_W + G * 8 + dw] =
            (uint32_t)(b0 & 0xff) | ((uint32_t)(b1 & 0xff) << 8)
          | ((uint32_t)(b2 & 0xff) << 16) | ((uint32_t)(b3 & 0xff) << 24);
    }
    __syncthreads();   // zf reads done; qd region may now be overwritten

    // ---- B chunk loader: chunk c -> ntile c>>2, k64-chunk c&3, buffer c&3 ----
    auto load_chunk = [&](int c) {
        if (tid < 512) {
            int nt = c >> 2, kc = c & 3;
            const char* src0 = (const char*)g_cb8 + (size_t)nt * 128 * 256 + kc * 64;
            uint32_t bbase = sbu + SBB + (c & 3) * BBUF_BYTES;
            int n = tid >> 2, seg = tid & 3;
            CP16(bbase + n * 80 + seg * 16, src0 + (size_t)n * 256 + seg * 16);
        }
    };
    load_chunk(0); CP_COMMIT();
    load_chunk(1); CP_COMMIT();
    load_chunk(2); CP_COMMIT();

    int acc[2][4];
    #pragma unroll
    for (int j = 0; j < 2; j++)
        #pragma unroll
        for (int e = 0; e < 4; e++) acc[j][e] = 0;

    const int r0 = mw + lq;
    const float inv0 = invs[r0], inv1 = invs[r0 + 8];

    for (int c = 0; c < 32; c++) {
        const int nt = c >> 2, kc = c & 3;
        CP_WAIT2();           // chunk c resident (per-thread)
        __syncthreads();      // all threads' waits done; buffer (c-1)&3 free
        if (c + 3 < 32) load_chunk(c + 3);
        CP_COMMIT();          // uniform group cadence

        const uint32_t* Bw = (const uint32_t*)(smem + SBB + (c & 3) * BBUF_BYTES);
        #pragma unroll
        for (int g = 0; g < 2; g++) {
            const int aw = (kc * 2 + g) * 8 + 2 * q;
            uint2 A0 = *(const uint2*)(a8w + r0 * A8_STRIDE_W + aw);
            uint2 A1 = *(const uint2*)(a8w + (r0 + 8) * A8_STRIDE_W + aw);
            #pragma unroll
            for (int j = 0; j < 2; j++) {
                int nl = nw + 8 * j + lq;
                uint2 B0 = *(const uint2*)(Bw + nl * B_STRIDE_W + g * 8 + 2 * q);
                mma_s8(acc[j][0], acc[j][1], acc[j][2], acc[j][3],
                       A0.x, A1.x, A0.y, A1.y, B0.x, B0.y);
            }
        }

        if (kc == 3) {
            // q16 = round((e2 - 2*isum*inv) * 2^15)
            #pragma unroll
            for (int j = 0; j < 2; j++) {
                int col0 = nt * 128 + nw + 8 * j + 2 * q;
                float e20 = e2s[col0], e21 = e2s[col0 + 1];
                int wIdx = (col0 >> 1);
                #pragma unroll
                for (int h = 0; h < 2; h++) {
                    float inv = h ? inv1 : inv0;
                    float s0 = e20 - 2.0f * ((float)acc[j][h * 2 + 0] * inv);
                    float s1 = e21 - 2.0f * ((float)acc[j][h * 2 + 1] * inv);
                    int q0 = max(-32767, min(32767, __float2int_rn(s0 * 32768.0f)));
                    int q1 = max(-32767, min(32767, __float2int_rn(s1 * 32768.0f)));
                    qd[(r0 + 8 * h) * QD_STRIDE_W + wIdx] =
                        ((uint32_t)(q1 & 0xffff) << 16) | (uint32_t)(q0 & 0xffff);
                    acc[j][h * 2 + 0] = 0;
                    acc[j][h * 2 + 1] = 0;
                }
            }
        }
    }
    __syncthreads();

    // ---- per-row FINAL min + capture (warp w owns rows 2w..2w+1, uint4 loads) ----
    for (int rr = 0; rr < 2; rr++) {
        int r = wid * 2 + rr;
        const uint4* row4 = (const uint4*)(qd + r * QD_STRIDE_W);
        uint4 v[4];
        int mn = 0x7fffffff;
        #pragma unroll
        for (int i = 0; i < 4; i++) {
            v[i] = row4[lane + 32 * i];
            const uint32_t* vw = (const uint32_t*)&v[i];
            #pragma unroll
            for (int w = 0; w < 4; w++) {
                int a = (int)(short)(vw[w] & 0xffff);
                int b = (int)(short)(vw[w] >> 16);
                mn = min(mn, min(a, b));
            }
        }
        #pragma unroll
        for (int o = 16; o; o >>= 1) mn = min(mn, __shfl_xor_sync(0xffffffffu, mn, o));
        int thr = mn + wqs[r];
        #pragma unroll
        for (int i = 0; i < 4; i++) {
            const uint32_t* vw = (const uint32_t*)&v[i];
            #pragma unroll
            for (int w = 0; w < 4; w++) {
                int a = (int)(short)(vw[w] & 0xffff);
                int b = (int)(short)(vw[w] >> 16);
                int colw = (lane + 32 * i) * 4 + w;
                if (a <= thr) {
                    int p = atomicAdd(&ccnt[r], 1);
                    if (p < CCAP) clist[r * CCAP + p] = 2 * colw;
                }
                if (b <= thr) {
                    int p = atomicAdd(&ccnt[r], 1);
                    if (p < CCAP) clist[r * CCAP + p] = 2 * colw + 1;
                }
            }
        }
    }
    __syncthreads();

    // ---- warp-parallel exact fp32 rescue (warp w owns rows 2w..2w+1) ----
    for (int rr = 0; rr < 2; rr++) {
        int r = wid * 2 + rr;
        const float z2f = z2s[r];
        const float* zr = z + (size_t)(m0 + r) * DIM;
        float zv[8];
        #pragma unroll
        for (int i = 0; i < 8; i++) zv[i] = zr[lane + 32 * i];

        float best = CUDART_INF_F; int bi = 0x7fffffff;
        int cnt = ccnt[r];
        int n_check = (cnt <= CCAP) ? cnt : NE;
        for (int p = 0; p < n_check; p++) {
            int cidx = (cnt <= CCAP) ? clist[r * CCAP + p] : p;
            const float* cr = cb + (size_t)cidx * DIM;
            float part = 0.0f;
            #pragma unroll
            for (int i = 0; i < 8; i++)
                part = fmaf(zv[i], __ldg(cr + lane + 32 * i), part);
            #pragma unroll
            for (int o = 16; o; o >>= 1)
                part += __shfl_xor_sync(0xffffffffu, part, o);
            float dd = (z2f - 2.0f * part) + e2s[cidx];
            if (dd < best || (dd == best && cidx < bi)) { best = dd; bi = cidx; }
        }
        if (lane == 0) bi_s[r] = bi;
    }
    __syncthreads();

    // ---- write indices output; epilogue handled by vq_epi_kernel ----
    if (tid < MCTA)
        out[(size_t)NT * DIM + 1 + m0 + tid] = (float)bi_s[tid];
}

// ---------------- epilogue: z_q_st (exact ST rounding) + loss, memory-bound ----------------
__global__ __launch_bounds__(256) void vq_epi_kernel(
    const float* __restrict__ z,
    const float* __restrict__ cb,
    float* __restrict__ out)
{
    __shared__ double red[256];
    __shared__ int idx_s[16];
    const int tid = threadIdx.x;
    const int r0  = blockIdx.x * 16;     // 16 rows per block, grid 4096

    if (tid < 16)
        idx_s[tid] = (int)out[(size_t)NT * DIM + 1 + r0 + tid];
    __syncthreads();

    float lacc = 0.0f;
    #pragma unroll 4
    for (int it = 0; it < 16; it++) {
        int row = r0 + it;
        float zv = z[(size_t)row * DIM + tid];
        float e  = __ldg(cb + (size_t)idx_s[it] * DIM + tid);
        float dq = e - zv;                  // fl(z_q - z)
        float o  = zv + dq;                 // fl(z + fl(z_q - z))
        out[(size_t)row * DIM + tid] = o;
        lacc = fmaf(dq, dq, lacc);
    }
    red[tid] = (double)lacc;
    __syncthreads();
    #pragma unroll
    for (int s = 128; s > 0; s >>= 1) {
        if (tid < s) red[tid] += red[tid + s];
        __syncthreads();
    }
    if (tid == 0) atomicAdd(&g_loss_acc, red[0]);
}

__global__ void vq_loss_kernel(float* __restrict__ out) {
    out[(size_t)NT * DIM] = (float)(1.25 * g_loss_acc / ((double)NT * (double)DIM));
}

// ---------------------------------------------------------------------------
extern "C" void kernel_launch(void* const* d_in, const int* in_sizes, int n_in,
                              void* d_out, int out_size) {
    const float *z, *cb;
    if (in_sizes[0] == NT * DIM) { z = (const float*)d_in[0]; cb = (const float*)d_in[1]; }
    else                         { z = (const float*)d_in[1]; cb = (const float*)d_in[0]; }
    float* out = (float*)d_out;

    cudaFuncSetAttribute(vq_main_kernel,
                         cudaFuncAttributeMaxDynamicSharedMemorySize, SMEM_TOTAL);

    vq_prep1_kernel<<<32, 256>>>(cb);
    vq_prep2_kernel<<<32, 256>>>(cb);
    vq_main_kernel<<<NT / MCTA, BLOCK, SMEM_TOTAL>>>(z, cb, out);
    vq_epi_kernel<<<NT / 16, 256>>>(z, cb, out);
    vq_loss_kernel<<<1, 1>>>(out);
}

// round 17
// speedup vs baseline: 5.4375x; 1.0064x over previous
#include <cuda_runtime.h>
#include <cstdint>
#include <math_constants.h>

#define NT     65536
#define DIM    256
#define NE     1024
#define MCTA   64
#define BLOCK  1024
#define CCAP   48

// ---------------- smem layout (bytes) ----------------
#define SA8   0              // z tile int8: 64 rows x 72 words (pair-permuted)   18432
#define SBB   18432          // 4 B chunk buffers x 10240 (k64 chunks)            40960
#define SQD   59392          // qd s16 pairs; pre-mainloop overlay: z fp32 tile   132096
#define SE2   191488         // e2 all 1024 f32                                    4096
#define SZ2   195584         // row norms f32 [64]                                  256
#define SINV  195840         // per-row inv dot scale f32 [64]                      256
#define SWQ   196096         // per-row capture window (q units) [64] int           256
#define SSZ   196352         // per-row z quant scale f32 [64]                      256
#define SCN   196608         // cand count [64] int                                 256
#define SBI   196864         // best index [64] int                                 256
#define SCL   197120         // cand list [64][CCAP] int (12288); later: loss red [1024] double (8192)
#define SMEM_TOTAL 209408

#define A8_STRIDE_W  72
#define B_STRIDE_W   20      // 16 data + 4 pad words per code row in chunk
#define BBUF_BYTES   10240
#define QD_STRIDE_W  516
#define ZF_STRIDE    260     // fp32 z staging stride (floats)

__device__ double g_loss_acc;
__device__ float  g_e2[NE];
__device__ unsigned g_cbmax_bits;
__device__ unsigned g_scmax_bits;
// pair-permuted int8 codebook: per code 256 bytes = 8 groups of 32 k;
// within each group's 8 words, stored[2q]=orig[q], stored[2q+1]=orig[q+4]
__device__ __align__(16) signed char g_cb8[NE * DIM];

#define CP16(dst, src) asm volatile("cp.async.cg.shared.global [%0], [%1], 16;" :: "r"(dst), "l"(src) : "memory")
#define CP_COMMIT()    asm volatile("cp.async.commit_group;" ::: "memory")
#define CP_WAIT2()     asm volatile("cp.async.wait_group 2;" ::: "memory")

__device__ __forceinline__ uint32_t smem_u32(const void* p) {
    uint32_t a;
    asm("{ .reg .u64 t; cvta.to.shared.u64 t, %1; cvt.u32.u64 %0, t; }" : "=r"(a) : "l"(p));
    return a;
}

__device__ __forceinline__ void mma_s8(int& c0, int& c1, int& c2, int& c3,
                                       uint32_t a0, uint32_t a1, uint32_t a2, uint32_t a3,
                                       uint32_t b0, uint32_t b1) {
    asm volatile("mma.sync.aligned.m16n8k32.row.col.s32.s8.s8.s32 "
                 "{%0,%1,%2,%3},{%4,%5,%6,%7},{%8,%9},{%0,%1,%2,%3};"
                 : "+r"(c0), "+r"(c1), "+r"(c2), "+r"(c3)
                 : "r"(a0), "r"(a1), "r"(a2), "r"(a3), "r"(b0), "r"(b1));
}

__device__ __forceinline__ int quant8(float v, float s) {
    int x = __float2int_rn(v * s);
    return max(-127, min(127, x));
}

// ---------------- prep1: e2 (fp64) + cb stats + zero loss ----------------
__global__ void vq_prep1_kernel(const float* __restrict__ cb) {
    int tid = threadIdx.x, lane = tid & 31;
    if (blockIdx.x == 0 && tid == 0) g_loss_acc = 0.0;
    int gw = blockIdx.x * 8 + (tid >> 5);
    #pragma unroll
    for (int i = 0; i < 4; i++) {
        int c = gw * 4 + i;
        const float* row = cb + (size_t)c * DIM;
        double s = 0.0; float sa = 0.0f, mx = 0.0f;
        #pragma unroll
        for (int j = 0; j < 8; j++) {
            float v = row[lane + 32 * j];
            s += (double)v * (double)v;
            sa += fabsf(v);
            mx = fmaxf(mx, fabsf(v));
        }
        #pragma unroll
        for (int o = 16; o; o >>= 1) {
            s  += __shfl_xor_sync(0xffffffffu, s, o);
            sa += __shfl_xor_sync(0xffffffffu, sa, o);
            mx = fmaxf(mx, __shfl_xor_sync(0xffffffffu, mx, o));
        }
        if (lane == 0) {
            g_e2[c] = (float)s;
            atomicMax(&g_cbmax_bits, __float_as_uint(mx));
            atomicMax(&g_scmax_bits, __float_as_uint(sa));
        }
    }
}

// ---------------- prep2: quantize codebook int8 pair-permuted ----------------
__global__ void vq_prep2_kernel(const float* __restrict__ cb) {
    float cbmax = __uint_as_float(g_cbmax_bits);
    float sc = (cbmax > 0.0f) ? 126.0f / cbmax : 1.0f;
    uint32_t* out8 = (uint32_t*)g_cb8;
    int base = blockIdx.x * 256 + threadIdx.x;
    #pragma unroll
    for (int i = 0; i < 8; i++) {
        int w = base + i * 8192;
        int n = w >> 6, m = w & 63;
        int G = m >> 3, p = m & 7;
        int o = (p & 1) ? ((p >> 1) + 4) : (p >> 1);
        int k0 = G * 32 + o * 4;
        const float* src = cb + (size_t)n * DIM + k0;
        int b0 = quant8(src[0], sc), b1 = quant8(src[1], sc);
        int b2 = quant8(src[2], sc), b3 = quant8(src[3], sc);
        out8[w] = (uint32_t)(b0 & 0xff) | ((uint32_t)(b1 & 0xff) << 8)
                | ((uint32_t)(b2 & 0xff) << 16) | ((uint32_t)(b3 & 0xff) << 24);
    }
}

// ---------------- main: 1024 threads, 32 warps (4 M x 8 N) ----------------
__global__ __launch_bounds__(BLOCK) void vq_main_kernel(
    const float* __restrict__ z,
    const float* __restrict__ cb,
    float* __restrict__ out)
{
    extern __shared__ char smem[];
    const uint32_t sbu = smem_u32(smem);
    uint32_t* a8w   = (uint32_t*)(smem + SA8);
    uint32_t* qd    = (uint32_t*)(smem + SQD);
    float*    zf    = (float*)(smem + SQD);     // pre-mainloop overlay
    float*    e2s   = (float*)(smem + SE2);
    float*    z2s   = (float*)(smem + SZ2);
    float*    invs  = (float*)(smem + SINV);
    int*      wqs   = (int*)(smem + SWQ);
    float*    szs   = (float*)(smem + SSZ);
    int*      ccnt  = (int*)(smem + SCN);
    int*      bi_s  = (int*)(smem + SBI);
    int*      clist = (int*)(smem + SCL);

    const int tid  = threadIdx.x;
    const int wid  = tid >> 5;
    const int lane = tid & 31;
    const int q    = lane & 3;
    const int lq   = lane >> 2;
    const int m0   = blockIdx.x * MCTA;
    const int mw   = (wid & 3) * 16;     // warp M base (4 warps in M)
    const int nw   = (wid >> 2) * 16;    // warp N base within 128-ntile (8 warps in N)

    const float cbmax = __uint_as_float(g_cbmax_bits);
    const float scmax = __uint_as_float(g_scmax_bits);
    const float sc  = (cbmax > 0.0f) ? 126.0f / cbmax : 1.0f;
    const float dcq = 0.5f / sc;

    // ---- stage z fp32 tile (single coalesced global pass), e2 table ----
    e2s[tid] = g_e2[tid];
    if (tid < MCTA) ccnt[tid] = 0;
    #pragma unroll
    for (int i = 0; i < 4; i++) {
        int s = i * BLOCK + tid;         // 4096 float4
        int row = s >> 6, c4 = s & 63;
        float4 v = *(const float4*)(z + (size_t)(m0 + row) * DIM + c4 * 4);
        *(float4*)(zf + row * ZF_STRIDE + c4 * 4) = v;
    }
    __syncthreads();

    // ---- per-row stats from smem (fp64 z2, sum|z|, max|z|): warp w owns rows 2w..2w+1 ----
    #pragma unroll
    for (int rr = 0; rr < 2; rr++) {
        int r = wid * 2 + rr;
        const float* zr = zf + r * ZF_STRIDE;
        double s = 0.0; float sa = 0.0f, mx = 0.0f;
        #pragma unroll
        for (int i = 0; i < 8; i++) {
            float v = zr[lane + 32 * i];
            s += (double)v * (double)v;
            sa += fabsf(v);
            mx = fmaxf(mx, fabsf(v));
        }
        #pragma unroll
        for (int o = 16; o; o >>= 1) {
            s  += __shfl_xor_sync(0xffffffffu, s, o);
            sa += __shfl_xor_sync(0xffffffffu, sa, o);
            mx = fmaxf(mx, __shfl_xor_sync(0xffffffffu, mx, o));
        }
        if (lane == 0) {
            float sz = (mx > 0.0f) ? 126.0f / mx : 1.0f;
            float dzr = 0.5f / sz;
            float E = dzr * scmax + dcq * sa + 256.0f * dzr * dcq;  // hard dot-err bound
            z2s[r]  = (float)s;
            szs[r]  = sz;
            invs[r] = 1.0f / (sz * sc);
            wqs[r]  = (int)(4.0f * E * 32768.0f) + 8;
        }
    }
    __syncthreads();

    // ---- stage A int8 pair-permuted from smem fp32 (4096 words) ----
    #pragma unroll
    for (int i = 0; i < 4; i++) {
        int s = i * BLOCK + tid;
        int row = s >> 6, ow = s & 63;
        int G = ow >> 3, o = ow & 7;
        int k0 = G * 32 + o * 4;
        float sz = szs[row];
        const float* src = zf + row * ZF_STRIDE + k0;
        int b0 = quant8(src[0], sz), b1 = quant8(src[1], sz);
        int b2 = quant8(src[2], sz), b3 = quant8(src[3], sz);
        int dw = (o < 4) ? 2 * o : 2 * (o - 4) + 1;
        a8w[row * A8_STRIDE_W + G * 8 + dw] =
            (uint32_t)(b0 & 0xff) | ((uint32_t)(b1 & 0xff) << 8)
          | ((uint32_t)(b2 & 0xff) << 16) | ((uint32_t)(b3 & 0xff) << 24);
    }
    __syncthreads();   // zf reads done; qd region may now be overwritten

    // ---- B chunk loader: chunk c -> ntile c>>2, k64-chunk c&3, buffer c&3 ----
    auto load_chunk = [&](int c) {
        if (tid < 512) {
            int nt = c >> 2, kc = c & 3;
            const char* src0 = (const char*)g_cb8 + (size_t)nt * 128 * 256 + kc * 64;
            uint32_t bbase = sbu + SBB + (c & 3) * BBUF_BYTES;
            int n = tid >> 2, seg = tid & 3;
            CP16(bbase + n * 80 + seg * 16, src0 + (size_t)n * 256 + seg * 16);
        }
    };
    load_chunk(0); CP_COMMIT();
    load_chunk(1); CP_COMMIT();
    load_chunk(2); CP_COMMIT();

    int acc[2][4];
    #pragma unroll
    for (int j = 0; j < 2; j++)
        #pragma unroll
        for (int e = 0; e < 4; e++) acc[j][e] = 0;

    const int r0 = mw + lq;
    const float inv0 = invs[r0], inv1 = invs[r0 + 8];

    for (int c = 0; c < 32; c++) {
        const int nt = c >> 2, kc = c & 3;
        CP_WAIT2();           // chunk c resident (per-thread)
        __syncthreads();      // all threads' waits done; buffer (c-1)&3 free
        if (c + 3 < 32) load_chunk(c + 3);
        CP_COMMIT();          // uniform group cadence

        const uint32_t* Bw = (const uint32_t*)(smem + SBB + (c & 3) * BBUF_BYTES);
        #pragma unroll
        for (int g = 0; g < 2; g++) {
            const int aw = (kc * 2 + g) * 8 + 2 * q;
            uint2 A0 = *(const uint2*)(a8w + r0 * A8_STRIDE_W + aw);
            uint2 A1 = *(const uint2*)(a8w + (r0 + 8) * A8_STRIDE_W + aw);
            #pragma unroll
            for (int j = 0; j < 2; j++) {
                int nl = nw + 8 * j + lq;
                uint2 B0 = *(const uint2*)(Bw + nl * B_STRIDE_W + g * 8 + 2 * q);
                mma_s8(acc[j][0], acc[j][1], acc[j][2], acc[j][3],
                       A0.x, A1.x, A0.y, A1.y, B0.x, B0.y);
            }
        }

        if (kc == 3) {
            // q16 = round((e2 - 2*isum*inv) * 2^15)
            #pragma unroll
            for (int j = 0; j < 2; j++) {
                int col0 = nt * 128 + nw + 8 * j + 2 * q;
                float e20 = e2s[col0], e21 = e2s[col0 + 1];
                int wIdx = (col0 >> 1);
                #pragma unroll
                for (int h = 0; h < 2; h++) {
                    float inv = h ? inv1 : inv0;
                    float s0 = e20 - 2.0f * ((float)acc[j][h * 2 + 0] * inv);
                    float s1 = e21 - 2.0f * ((float)acc[j][h * 2 + 1] * inv);
                    int q0 = max(-32767, min(32767, __float2int_rn(s0 * 32768.0f)));
                    int q1 = max(-32767, min(32767, __float2int_rn(s1 * 32768.0f)));
                    qd[(r0 + 8 * h) * QD_STRIDE_W + wIdx] =
                        ((uint32_t)(q1 & 0xffff) << 16) | (uint32_t)(q0 & 0xffff);
                    acc[j][h * 2 + 0] = 0;
                    acc[j][h * 2 + 1] = 0;
                }
            }
        }
    }
    __syncthreads();

    // ---- per-row FINAL min + capture (warp w owns rows 2w..2w+1, uint4 loads) ----
    for (int rr = 0; rr < 2; rr++) {
        int r = wid * 2 + rr;
        const uint4* row4 = (const uint4*)(qd + r * QD_STRIDE_W);
        uint4 v[4];
        int mn = 0x7fffffff;
        #pragma unroll
        for (int i = 0; i < 4; i++) {
            v[i] = row4[lane + 32 * i];
            const uint32_t* vw = (const uint32_t*)&v[i];
            #pragma unroll
            for (int w = 0; w < 4; w++) {
                int a = (int)(short)(vw[w] & 0xffff);
                int b = (int)(short)(vw[w] >> 16);
                mn = min(mn, min(a, b));
            }
        }
        #pragma unroll
        for (int o = 16; o; o >>= 1) mn = min(mn, __shfl_xor_sync(0xffffffffu, mn, o));
        int thr = mn + wqs[r];
        #pragma unroll
        for (int i = 0; i < 4; i++) {
            const uint32_t* vw = (const uint32_t*)&v[i];
            #pragma unroll
            for (int w = 0; w < 4; w++) {
                int a = (int)(short)(vw[w] & 0xffff);
                int b = (int)(short)(vw[w] >> 16);
                int colw = (lane + 32 * i) * 4 + w;
                if (a <= thr) {
                    int p = atomicAdd(&ccnt[r], 1);
                    if (p < CCAP) clist[r * CCAP + p] = 2 * colw;
                }
                if (b <= thr) {
                    int p = atomicAdd(&ccnt[r], 1);
                    if (p < CCAP) clist[r * CCAP + p] = 2 * colw + 1;
                }
            }
        }
    }
    __syncthreads();

    // ---- warp-parallel exact fp32 rescue (warp w owns rows 2w..2w+1) ----
    for (int rr = 0; rr < 2; rr++) {
        int r = wid * 2 + rr;
        const float z2f = z2s[r];
        const float* zr = z + (size_t)(m0 + r) * DIM;
        float zv[8];
        #pragma unroll
        for (int i = 0; i < 8; i++) zv[i] = zr[lane + 32 * i];

        float best = CUDART_INF_F; int bi = 0x7fffffff;
        int cnt = ccnt[r];
        int n_check = (cnt <= CCAP) ? cnt : NE;
        for (int p = 0; p < n_check; p++) {
            int cidx = (cnt <= CCAP) ? clist[r * CCAP + p] : p;
            const float* cr = cb + (size_t)cidx * DIM;
            float part = 0.0f;
            #pragma unroll
            for (int i = 0; i < 8; i++)
                part = fmaf(zv[i], __ldg(cr + lane + 32 * i), part);
            #pragma unroll
            for (int o = 16; o; o >>= 1)
                part += __shfl_xor_sync(0xffffffffu, part, o);
            float dd = (z2f - 2.0f * part) + e2s[cidx];
            if (dd < best || (dd == best && cidx < bi)) { best = dd; bi = cidx; }
        }
        if (lane == 0) bi_s[r] = bi;
    }
    __syncthreads();   // bi_s ready; clist dead -> reuse as loss reduction

    // ---- fused epilogue: float4 z_q_st (exact ST rounding), indices, loss ----
    const int rg = tid >> 6;        // 0..15 row group
    const int c4 = tid & 63;        // float4 column
    float lacc = 0.0f;
    #pragma unroll
    for (int it = 0; it < 4; it++) {
        int row = it * 16 + rg;
        float4 zv = *(const float4*)(z + (size_t)(m0 + row) * DIM + c4 * 4);
        float4 e  = *(const float4*)(cb + (size_t)bi_s[row] * DIM + c4 * 4);
        float d0 = e.x - zv.x, d1 = e.y - zv.y, d2 = e.z - zv.z, d3 = e.w - zv.w;
        float4 o = make_float4(zv.x + d0, zv.y + d1, zv.z + d2, zv.w + d3);
        *(float4*)(out + (size_t)(m0 + row) * DIM + c4 * 4) = o;
        lacc = fmaf(d0, d0, lacc);
        lacc = fmaf(d1, d1, lacc);
        lacc = fmaf(d2, d2, lacc);
        lacc = fmaf(d3, d3, lacc);
    }
    if (tid < MCTA)
        out[(size_t)NT * DIM + 1 + m0 + tid] = (float)bi_s[tid];

    double* red = (double*)(smem + SCL);
    red[tid] = (double)lacc;
    __syncthreads();
    #pragma unroll
    for (int s = 512; s > 0; s >>= 1) {
        if (tid < s) red[tid] += red[tid + s];
        __syncthreads();
    }
    if (tid == 0) atomicAdd(&g_loss_acc, red[0]);
}

__global__ void vq_loss_kernel(float* __restrict__ out) {
    out[(size_t)NT * DIM] = (float)(1.25 * g_loss_acc / ((double)NT * (double)DIM));
}

// ---------------------------------------------------------------------------
extern "C" void kernel_launch(void* const* d_in, const int* in_sizes, int n_in,
                              void* d_out, int out_size) {
    const float *z, *cb;
    if (in_sizes[0] == NT * DIM) { z = (const float*)d_in[0]; cb = (const float*)d_in[1]; }
    else                         { z = (const float*)d_in[1]; cb = (const float*)d_in[0]; }
    float* out = (float*)d_out;

    cudaFuncSetAttribute(vq_main_kernel,
                         cudaFuncAttributeMaxDynamicSharedMemorySize, SMEM_TOTAL);

    vq_prep1_kernel<<<32, 256>>>(cb);
    vq_prep2_kernel<<<32, 256>>>(cb);
    vq_main_kernel<<<NT / MCTA, BLOCK, SMEM_TOTAL>>>(z, cb, out);
    vq_loss_kernel<<<1, 1>>>(out);
}